// round 13
// baseline (speedup 1.0000x reference)
#include <cuda_runtime.h>
#include <math.h>

#define S_LEN 128
#define BATCH 64
#define EMB   256
#define HID_H 256
#define NHID  30

typedef unsigned long long ull;

// ---------------- f32x2 helpers (FFMA2/FADD2 only reachable via PTX) ----------------
__device__ __forceinline__ ull fma2(ull a, ull b, ull c) {
    ull d;
    asm("fma.rn.f32x2 %0, %1, %2, %3;" : "=l"(d) : "l"(a), "l"(b), "l"(c));
    return d;
}
__device__ __forceinline__ ull add2(ull a, ull b) {
    ull d;
    asm("add.rn.f32x2 %0, %1, %2;" : "=l"(d) : "l"(a), "l"(b));
    return d;
}
__device__ __forceinline__ ull pack2(float lo, float hi) {
    ull d;
    asm("mov.b64 %0, {%1, %2};" : "=l"(d) : "f"(lo), "f"(hi));
    return d;
}
__device__ __forceinline__ void unpack2(ull v, float& lo, float& hi) {
    asm("mov.b64 {%0, %1}, %2;" : "=f"(lo), "=f"(hi) : "l"(v));
}

// ---------------- scratch (device globals; no allocation allowed) ----------------
__device__ float g_X[S_LEN * 2 * 1024 * BATCH];                 // 64 MB
// h ping-pong (R11 layout): (((par*2+dir)*2+bhalf)*256 + hid)*32 + b32
__device__ float g_h[2 * 2 * 2 * 256 * 32];                     // 256 KB
__device__ float g_enc[BATCH * S_LEN * 512];                    // 16.8 MB
__device__ float g_uw[BATCH * S_LEN * 64];                      // 2 MB
// grid barrier: [grp 0..3][step 0..128]  (R11 structure)
__device__ int g_bar2[4 * 129];

// ---------------- barrier reset ----------------
__global__ void zerobar_kernel() {
    for (int i = threadIdx.x; i < 4 * 129; i += blockDim.x) g_bar2[i] = 0;
}

// ---------------- stage 1: pre-gates GEMM, f32x2, fused embedding gather ----------------
// (byte-identical to R11)
__global__ void __launch_bounds__(256) pregemm_kernel(
    const int* __restrict__ concepts, const int* __restrict__ lens,
    const float* __restrict__ embedding,
    const float* __restrict__ Wih_f, const float* __restrict__ b_f,
    const float* __restrict__ Wih_b, const float* __restrict__ b_b)
{
    __shared__ ull A2[16 * 130];
    __shared__ ull B2[16 * 34];
    __shared__ int tok_s[64];

    int t = blockIdx.y;
    int rowbase = blockIdx.x * 128;
    int dir = rowbase >> 10;
    int row0 = rowbase & 1023;
    const float* W    = dir ? Wih_b : Wih_f;
    const float* bias = dir ? b_b   : b_f;
    int tid = threadIdx.x;

    if (tid < 64) {
        int b = tid;
        int srow = t;
        if (dir) { int L = lens[b]; srow = (t < L) ? (L - 1 - t) : t; }
        tok_s[b] = concepts[srow * 64 + b];
    }
    __syncthreads();

    int tx = tid & 15, ty = tid >> 4;
    ull acc[8][2];
    #pragma unroll
    for (int i = 0; i < 8; i++) { acc[i][0] = 0ull; acc[i][1] = 0ull; }

    for (int k0 = 0; k0 < 256; k0 += 16) {
        #pragma unroll
        for (int i = 0; i < 2; i++) {
            int fidx = i * 256 + tid;
            int m = fidx >> 2, q = fidx & 3;
            float4 w4 = *(const float4*)&W[(row0 + m) * 256 + k0 + q * 4];
            A2[(q * 4 + 0) * 130 + m] = pack2(w4.x, w4.x);
            A2[(q * 4 + 1) * 130 + m] = pack2(w4.y, w4.y);
            A2[(q * 4 + 2) * 130 + m] = pack2(w4.z, w4.z);
            A2[(q * 4 + 3) * 130 + m] = pack2(w4.w, w4.w);
        }
        #pragma unroll
        for (int i = 0; i < 2; i++) {
            int fidx = i * 256 + tid;
            int bp = fidx >> 4, k = fidx & 15;
            float v0 = embedding[(long)tok_s[2 * bp]     * 256 + k0 + k];
            float v1 = embedding[(long)tok_s[2 * bp + 1] * 256 + k0 + k];
            B2[k * 34 + bp] = pack2(v0, v1);
        }
        __syncthreads();
        #pragma unroll
        for (int k = 0; k < 16; k++) {
            ulonglong2 bb = *(const ulonglong2*)&B2[k * 34 + tx * 2];
            #pragma unroll
            for (int u = 0; u < 4; u++) {
                ulonglong2 a = *(const ulonglong2*)&A2[k * 130 + ty * 8 + u * 2];
                acc[u * 2    ][0] = fma2(a.x, bb.x, acc[u * 2    ][0]);
                acc[u * 2    ][1] = fma2(a.x, bb.y, acc[u * 2    ][1]);
                acc[u * 2 + 1][0] = fma2(a.y, bb.x, acc[u * 2 + 1][0]);
                acc[u * 2 + 1][1] = fma2(a.y, bb.y, acc[u * 2 + 1][1]);
            }
        }
        __syncthreads();
    }

    #pragma unroll
    for (int i = 0; i < 8; i++) {
        int m = ty * 8 + i;
        float bv = bias[row0 + m];
        float x0, x1, x2, x3;
        unpack2(acc[i][0], x0, x1);
        unpack2(acc[i][1], x2, x3);
        float4 o = make_float4(x0 + bv, x1 + bv, x2 + bv, x3 + bv);
        *(float4*)&g_X[(((long)t * 2 + dir) * 1024 + row0 + m) * 64 + tx * 4] = o;
    }
}

// ---------------- stage 2: persistent LSTM recurrence v3 ----------------
// R11 decomposition + barrier protocol, FFMA2 inner compute.
// 128 CTAs: dir=cta>>6, bhalf=(cta&63)>>5, jgrp=cta&31 (8 hidden units).
// Threads: kh=tid>>7 (k half), j=(tid>>4)&7, bp=tid&15 (2 batches).
// smem: ws[4g][8j][256k] {w,w} pairs, h2[16bp][258] {h_b0,h_b1} pairs, red[128][4].
__global__ void __launch_bounds__(256, 1) recur_kernel(
    const float* __restrict__ Whh_f, const float* __restrict__ Whh_b,
    const int* __restrict__ lens)
{
    extern __shared__ ull sm2[];
    ull* ws  = sm2;                      // 8192 ull (64KB)
    ull* h2  = sm2 + 8192;               // 16*258 = 4128 ull
    ull* red = sm2 + 8192 + 4128;        // 128*4 = 512 ull
    // total 12832 ull = 102656 B

    int cta = blockIdx.x;
    int dir   = cta >> 6;
    int bhalf = (cta & 63) >> 5;
    int jgrp  = cta & 31;
    int tid = threadIdx.x;
    int kh = tid >> 7;
    int j  = (tid >> 4) & 7;
    int bp = tid & 15;
    int hidx = jgrp * 8 + j;
    int b0 = bhalf * 32 + bp * 2;
    int grp = dir * 2 + bhalf;
    const float* Whh = dir ? Whh_b : Whh_f;
    int L0 = lens[b0], L1 = lens[b0 + 1];

    // weight fill: ws[(g*8+r)*256+k] = {w,w} ; 8192 entries, 32 per thread
    for (int i = 0; i < 32; i++) {
        int idx = i * 256 + tid;
        int g = idx >> 11;
        int r = (idx >> 8) & 7;
        int k = idx & 255;
        float w = Whh[(g * 256 + jgrp * 8 + r) * 256 + k];
        ws[(g * 8 + r) * 256 + k] = pack2(w, w);
    }

    // init parity-1 h slot (t=0 reads parity 1); 256 entries via (tid>>5, tid&31)
    {
        int hid_i = jgrp * 8 + (tid >> 5);
        int b_i = tid & 31;
        g_h[(((1 * 2 + dir) * 2 + bhalf) * 256 + hid_i) * 32 + b_i] = 0.f;
    }
    __threadfence();
    __syncthreads();
    if (tid == 0) atomicAdd(&g_bar2[grp * 129 + 0], 1);

    float c0 = 0.f, c1 = 0.f;
    volatile int* barv = (volatile int*)g_bar2;
    const ull* w0p = ws + (0 * 8 + j) * 256 + kh * 128;
    const ull* w1p = ws + (1 * 8 + j) * 256 + kh * 128;
    const ull* w2p = ws + (2 * 8 + j) * 256 + kh * 128;
    const ull* w3p = ws + (3 * 8 + j) * 256 + kh * 128;
    const ull* hrow = h2 + bp * 258 + kh * 128;

    for (int t = 0; t < S_LEN; t++) {
        ull acc0 = 0ull, acc1 = 0ull, acc2 = 0ull, acc3 = 0ull;
        if (kh == 0) {      // X pre-load before barrier (g_X static after pregemm)
            long xb = ((long)t * 2 + dir) * 1024 * 64;
            float2 x0 = *(const float2*)&g_X[xb + (0   + hidx) * 64 + b0];
            float2 x1 = *(const float2*)&g_X[xb + (256 + hidx) * 64 + b0];
            float2 x2 = *(const float2*)&g_X[xb + (512 + hidx) * 64 + b0];
            float2 x3 = *(const float2*)&g_X[xb + (768 + hidx) * 64 + b0];
            acc0 = pack2(x0.x, x0.y);
            acc1 = pack2(x1.x, x1.y);
            acc2 = pack2(x2.x, x2.y);
            acc3 = pack2(x3.x, x3.y);
        }

        // tid0 pure spin on the step flag (proven R11 protocol)
        if (tid == 0) {
            while (barv[grp * 129 + t] < 32) { }
        }
        __syncthreads();
        __threadfence();

        // stage h_prev (parity (t+1)&1): [hid256][b32] -> batch-pair packed smem
        {
            int rp = (t + 1) & 1;
            const float* hp = &g_h[((rp * 2 + dir) * 2 + bhalf) * 8192];
            #pragma unroll
            for (int i = 0; i < 8; i++) {
                int fidx = i * 256 + tid;            // 2048 float4
                int k = fidx >> 3, bq = fidx & 7;
                float4 hv = __ldcg((const float4*)(hp + k * 32 + bq * 4));
                h2[(bq * 2 + 0) * 258 + k] = pack2(hv.x, hv.y);
                h2[(bq * 2 + 1) * 258 + k] = pack2(hv.z, hv.w);
            }
        }
        __syncthreads();

        #pragma unroll 8
        for (int k = 0; k < 128; k += 2) {
            ulonglong2 hA = *(const ulonglong2*)&hrow[k];
            ulonglong2 g0 = *(const ulonglong2*)&w0p[k];
            ulonglong2 g1 = *(const ulonglong2*)&w1p[k];
            ulonglong2 g2 = *(const ulonglong2*)&w2p[k];
            ulonglong2 g3 = *(const ulonglong2*)&w3p[k];
            acc0 = fma2(g0.x, hA.x, acc0); acc0 = fma2(g0.y, hA.y, acc0);
            acc1 = fma2(g1.x, hA.x, acc1); acc1 = fma2(g1.y, hA.y, acc1);
            acc2 = fma2(g2.x, hA.x, acc2); acc2 = fma2(g2.y, hA.y, acc2);
            acc3 = fma2(g3.x, hA.x, acc3); acc3 = fma2(g3.y, hA.y, acc3);
        }

        // k-half reduction through smem (CTA-local, sync-protected)
        if (kh == 1) {
            ull* rp2 = red + (tid & 127) * 4;
            rp2[0] = acc0; rp2[1] = acc1; rp2[2] = acc2; rp2[3] = acc3;
        }
        __syncthreads();

        if (kh == 0) {
            const ull* rp2 = red + tid * 4;
            acc0 = add2(acc0, rp2[0]);
            acc1 = add2(acc1, rp2[1]);
            acc2 = add2(acc2, rp2[2]);
            acc3 = add2(acc3, rp2[3]);

            float ai0, ai1, af0, af1, ag0, ag1, ao0, ao1;
            unpack2(acc0, ai0, ai1);
            unpack2(acc1, af0, af1);
            unpack2(acc2, ag0, ag1);
            unpack2(acc3, ao0, ao1);

            // batch b0
            float ig = __fdividef(1.f, 1.f + __expf(-ai0));
            float fg = __fdividef(1.f, 1.f + __expf(-af0));
            float gg = __fdividef(2.f, 1.f + __expf(-2.f * ag0)) - 1.f;
            float og = __fdividef(1.f, 1.f + __expf(-ao0));
            c0 = fg * c0 + ig * gg;
            float h0v = og * (__fdividef(2.f, 1.f + __expf(-2.f * c0)) - 1.f);
            // batch b1
            float ig1 = __fdividef(1.f, 1.f + __expf(-ai1));
            float fg1 = __fdividef(1.f, 1.f + __expf(-af1));
            float gg1 = __fdividef(2.f, 1.f + __expf(-2.f * ag1)) - 1.f;
            float og1 = __fdividef(1.f, 1.f + __expf(-ao1));
            c1 = fg1 * c1 + ig1 * gg1;
            float h1v = og1 * (__fdividef(2.f, 1.f + __expf(-2.f * c1)) - 1.f);

            // fused enc write (valid mask + backward un-reversal), per-batch L
            bool v0 = (t < L0);
            float e0 = v0 ? h0v : 0.f;
            bool v1 = (t < L1);
            float e1 = v1 ? h1v : 0.f;
            if (dir == 0) {
                g_enc[((long)b0 * 128 + t) * 512 + hidx] = e0;
                g_enc[((long)(b0 + 1) * 128 + t) * 512 + hidx] = e1;
            } else {
                int tp0 = v0 ? (L0 - 1 - t) : t;
                int tp1 = v1 ? (L1 - 1 - t) : t;
                g_enc[((long)b0 * 128 + tp0) * 512 + 256 + hidx] = e0;
                g_enc[((long)(b0 + 1) * 128 + tp1) * 512 + 256 + hidx] = e1;
            }

            if (t < S_LEN - 1) {
                int wp = t & 1;
                *(float2*)&g_h[(((wp * 2 + dir) * 2 + bhalf) * 256 + hidx) * 32 + bp * 2] =
                    make_float2(h0v, h1v);
            }
        }

        if (t < S_LEN - 1) {
            __threadfence();
            __syncthreads();
            if (tid == 0) atomicAdd(&g_bar2[grp * 129 + t + 1], 1);
        }
    }
}

// ---------------- stage 3: u/w projections (byte-identical to R11) ----------------
__global__ void __launch_bounds__(256) uw_kernel(
    const float* __restrict__ Ua, const float* __restrict__ Wa)
{
    __shared__ float A_s[64 * 72];
    __shared__ float B_s[64 * 72];
    int pos0 = blockIdx.x * 64;
    int tid = threadIdx.x;
    int tx = tid & 15, ty = tid >> 4;

    float acc[4][4];
    #pragma unroll
    for (int i = 0; i < 4; i++) { acc[i][0]=0.f; acc[i][1]=0.f; acc[i][2]=0.f; acc[i][3]=0.f; }

    for (int k0 = 0; k0 < 512; k0 += 64) {
        #pragma unroll
        for (int i = 0; i < 4; i++) {
            int fidx = i * 256 + tid;
            int m = fidx >> 4, kq = fidx & 15;
            float4 v = *(const float4*)&g_enc[(long)(pos0 + m) * 512 + k0 + kq * 4];
            *(float4*)&A_s[m * 72 + kq * 4] = v;
        }
        #pragma unroll
        for (int i = 0; i < 4; i++) {
            int fidx = i * 256 + tid;
            int cc = fidx >> 4, kq = fidx & 15;
            float4 v = make_float4(0.f, 0.f, 0.f, 0.f);
            if (cc < 30)      v = *(const float4*)&Ua[cc * 512 + k0 + kq * 4];
            else if (cc >= 32 && cc < 62) v = *(const float4*)&Wa[(cc - 32) * 512 + k0 + kq * 4];
            B_s[(kq * 4 + 0) * 72 + cc] = v.x;
            B_s[(kq * 4 + 1) * 72 + cc] = v.y;
            B_s[(kq * 4 + 2) * 72 + cc] = v.z;
            B_s[(kq * 4 + 3) * 72 + cc] = v.w;
        }
        __syncthreads();
        #pragma unroll 8
        for (int k = 0; k < 64; k++) {
            float4 b4 = *(const float4*)&B_s[k * 72 + tx * 4];
            #pragma unroll
            for (int i = 0; i < 4; i++) {
                float a = A_s[(ty * 4 + i) * 72 + k];
                acc[i][0] = fmaf(a, b4.x, acc[i][0]);
                acc[i][1] = fmaf(a, b4.y, acc[i][1]);
                acc[i][2] = fmaf(a, b4.z, acc[i][2]);
                acc[i][3] = fmaf(a, b4.w, acc[i][3]);
            }
        }
        __syncthreads();
    }
    #pragma unroll
    for (int i = 0; i < 4; i++) {
        *(float4*)&g_uw[(long)(pos0 + ty * 4 + i) * 64 + tx * 4] =
            make_float4(acc[i][0], acc[i][1], acc[i][2], acc[i][3]);
    }
}

// ---------------- stage 4: edge scores + predictions (byte-identical to R11) ----------------
__global__ void __launch_bounds__(256) scores_kernel(
    const float* __restrict__ va, float* __restrict__ out, long out_size)
{
    __shared__ float u_s[32 * 33];
    __shared__ float w_s[128 * 33];
    __shared__ float va_s[30];

    int b = blockIdx.y;
    int q0 = blockIdx.x * 32;
    int tid = threadIdx.x;

    for (int i = tid; i < 128 * 32; i += 256) {
        int k = i >> 5, h = i & 31;
        w_s[k * 33 + h] = g_uw[((long)b * 128 + k) * 64 + 32 + h];
    }
    for (int i = tid; i < 32 * 32; i += 256) {
        int q = i >> 5, h = i & 31;
        u_s[q * 33 + h] = g_uw[((long)b * 128 + q0 + q) * 64 + h];
    }
    if (tid < 30) va_s[tid] = va[tid];
    __syncthreads();

    int kk = tid & 127;
    int qoff = tid >> 7;
    bool preds = (out_size >= 2097152);
    #pragma unroll 1
    for (int i = 0; i < 16; i++) {
        int q = qoff * 16 + i;
        float s = 0.f;
        #pragma unroll
        for (int h = 0; h < 30; h++) {
            float x = u_s[q * 33 + h] + w_s[kk * 33 + h];
            float e = __expf(-2.f * x);
            float th = __fdividef(2.f, 1.f + e) - 1.f;
            s = fmaf(va_s[h], th, s);
        }
        long oidx = ((long)b * 128 + q0 + q) * 128 + kk;
        out[oidx] = s;
        if (preds) out[1048576 + oidx] = (s >= 0.f) ? 1.f : 0.f;
    }
}

// ---------------- launch ----------------
extern "C" void kernel_launch(void* const* d_in, const int* in_sizes, int n_in,
                              void* d_out, int out_size) {
    const int*   concepts  = (const int*)  d_in[0];
    const int*   lens      = (const int*)  d_in[1];
    const float* embedding = (const float*)d_in[2];
    const float* Wih_f     = (const float*)d_in[3];
    const float* Whh_f     = (const float*)d_in[4];
    const float* b_f       = (const float*)d_in[5];
    const float* Wih_b     = (const float*)d_in[6];
    const float* Whh_b     = (const float*)d_in[7];
    const float* b_b       = (const float*)d_in[8];
    const float* Ua        = (const float*)d_in[9];
    const float* Wa        = (const float*)d_in[10];
    const float* va        = (const float*)d_in[11];
    float* out = (float*)d_out;

    // smem: (8192 + 4128 + 512) ull = 12832 * 8 = 102656 bytes
    cudaFuncSetAttribute(recur_kernel, cudaFuncAttributeMaxDynamicSharedMemorySize, 102656);

    zerobar_kernel<<<1, 256>>>();
    pregemm_kernel<<<dim3(16, 128), 256>>>(concepts, lens, embedding,
                                           Wih_f, b_f, Wih_b, b_b);
    recur_kernel<<<128, 256, 102656>>>(Whh_f, Whh_b, lens);
    uw_kernel<<<128, 256>>>(Ua, Wa);
    scores_kernel<<<dim3(4, 64), 256>>>(va, out, (long)out_size);
}

// round 14
// speedup vs baseline: 1.0952x; 1.0952x over previous
#include <cuda_runtime.h>
#include <math.h>

#define S_LEN 128
#define BATCH 64
#define EMB   256
#define HID_H 256
#define NHID  30

typedef unsigned long long ull;

// ---------------- f32x2 helpers (FFMA2/FADD2 only reachable via PTX) ----------------
__device__ __forceinline__ ull fma2(ull a, ull b, ull c) {
    ull d;
    asm("fma.rn.f32x2 %0, %1, %2, %3;" : "=l"(d) : "l"(a), "l"(b), "l"(c));
    return d;
}
__device__ __forceinline__ ull add2(ull a, ull b) {
    ull d;
    asm("add.rn.f32x2 %0, %1, %2;" : "=l"(d) : "l"(a), "l"(b));
    return d;
}
__device__ __forceinline__ ull pack2(float lo, float hi) {
    ull d;
    asm("mov.b64 %0, {%1, %2};" : "=l"(d) : "f"(lo), "f"(hi));
    return d;
}
__device__ __forceinline__ void unpack2(ull v, float& lo, float& hi) {
    asm("mov.b64 {%0, %1}, %2;" : "=f"(lo), "=f"(hi) : "l"(v));
}

// ---------------- scratch (device globals; no allocation allowed) ----------------
__device__ float g_X[S_LEN * 2 * 1024 * BATCH];                 // 64 MB
// h ping-pong: (((par*2+dir)*2+bhalf)*256 + hid)*32 + b32
__device__ float g_h[2 * 2 * 2 * 256 * 32];                     // 256 KB
__device__ float g_enc[BATCH * S_LEN * 512];                    // 16.8 MB
__device__ float g_uw[BATCH * S_LEN * 64];                      // 2 MB
// grid barrier: [grp 0..3][step 0..128]
__device__ int g_bar2[4 * 129];

// ---------------- barrier reset ----------------
__global__ void zerobar_kernel() {
    for (int i = threadIdx.x; i < 4 * 129; i += blockDim.x) g_bar2[i] = 0;
}

// ---------------- ncu slot-shift dummy (no-op) ----------------
__global__ void dummy_kernel() {}

// ---------------- stage 1: pre-gates GEMM, f32x2, fused embedding gather ----------------
// (byte-identical to R13)
__global__ void __launch_bounds__(256) pregemm_kernel(
    const int* __restrict__ concepts, const int* __restrict__ lens,
    const float* __restrict__ embedding,
    const float* __restrict__ Wih_f, const float* __restrict__ b_f,
    const float* __restrict__ Wih_b, const float* __restrict__ b_b)
{
    __shared__ ull A2[16 * 130];
    __shared__ ull B2[16 * 34];
    __shared__ int tok_s[64];

    int t = blockIdx.y;
    int rowbase = blockIdx.x * 128;
    int dir = rowbase >> 10;
    int row0 = rowbase & 1023;
    const float* W    = dir ? Wih_b : Wih_f;
    const float* bias = dir ? b_b   : b_f;
    int tid = threadIdx.x;

    if (tid < 64) {
        int b = tid;
        int srow = t;
        if (dir) { int L = lens[b]; srow = (t < L) ? (L - 1 - t) : t; }
        tok_s[b] = concepts[srow * 64 + b];
    }
    __syncthreads();

    int tx = tid & 15, ty = tid >> 4;
    ull acc[8][2];
    #pragma unroll
    for (int i = 0; i < 8; i++) { acc[i][0] = 0ull; acc[i][1] = 0ull; }

    for (int k0 = 0; k0 < 256; k0 += 16) {
        #pragma unroll
        for (int i = 0; i < 2; i++) {
            int fidx = i * 256 + tid;
            int m = fidx >> 2, q = fidx & 3;
            float4 w4 = *(const float4*)&W[(row0 + m) * 256 + k0 + q * 4];
            A2[(q * 4 + 0) * 130 + m] = pack2(w4.x, w4.x);
            A2[(q * 4 + 1) * 130 + m] = pack2(w4.y, w4.y);
            A2[(q * 4 + 2) * 130 + m] = pack2(w4.z, w4.z);
            A2[(q * 4 + 3) * 130 + m] = pack2(w4.w, w4.w);
        }
        #pragma unroll
        for (int i = 0; i < 2; i++) {
            int fidx = i * 256 + tid;
            int bp = fidx >> 4, k = fidx & 15;
            float v0 = embedding[(long)tok_s[2 * bp]     * 256 + k0 + k];
            float v1 = embedding[(long)tok_s[2 * bp + 1] * 256 + k0 + k];
            B2[k * 34 + bp] = pack2(v0, v1);
        }
        __syncthreads();
        #pragma unroll
        for (int k = 0; k < 16; k++) {
            ulonglong2 bb = *(const ulonglong2*)&B2[k * 34 + tx * 2];
            #pragma unroll
            for (int u = 0; u < 4; u++) {
                ulonglong2 a = *(const ulonglong2*)&A2[k * 130 + ty * 8 + u * 2];
                acc[u * 2    ][0] = fma2(a.x, bb.x, acc[u * 2    ][0]);
                acc[u * 2    ][1] = fma2(a.x, bb.y, acc[u * 2    ][1]);
                acc[u * 2 + 1][0] = fma2(a.y, bb.x, acc[u * 2 + 1][0]);
                acc[u * 2 + 1][1] = fma2(a.y, bb.y, acc[u * 2 + 1][1]);
            }
        }
        __syncthreads();
    }

    #pragma unroll
    for (int i = 0; i < 8; i++) {
        int m = ty * 8 + i;
        float bv = bias[row0 + m];
        float x0, x1, x2, x3;
        unpack2(acc[i][0], x0, x1);
        unpack2(acc[i][1], x2, x3);
        float4 o = make_float4(x0 + bv, x1 + bv, x2 + bv, x3 + bv);
        *(float4*)&g_X[(((long)t * 2 + dir) * 1024 + row0 + m) * 64 + tx * 4] = o;
    }
}

// ---------------- stage 2: persistent LSTM recurrence (R13 + consumer fence removed) ----------------
// 128 CTAs: dir=cta>>6, bhalf=(cta&63)>>5, jgrp=cta&31 (8 hidden units).
// Threads: kh=tid>>7 (k half), j=(tid>>4)&7, bp=tid&15 (2 batches).
__global__ void __launch_bounds__(256, 1) recur_kernel(
    const float* __restrict__ Whh_f, const float* __restrict__ Whh_b,
    const int* __restrict__ lens)
{
    extern __shared__ ull sm2[];
    ull* ws  = sm2;                      // 8192 ull (64KB)
    ull* h2  = sm2 + 8192;               // 16*258 = 4128 ull
    ull* red = sm2 + 8192 + 4128;        // 128*4 = 512 ull
    // total 12832 ull = 102656 B

    int cta = blockIdx.x;
    int dir   = cta >> 6;
    int bhalf = (cta & 63) >> 5;
    int jgrp  = cta & 31;
    int tid = threadIdx.x;
    int kh = tid >> 7;
    int j  = (tid >> 4) & 7;
    int bp = tid & 15;
    int hidx = jgrp * 8 + j;
    int b0 = bhalf * 32 + bp * 2;
    int grp = dir * 2 + bhalf;
    const float* Whh = dir ? Whh_b : Whh_f;
    int L0 = lens[b0], L1 = lens[b0 + 1];

    // weight fill: ws[(g*8+r)*256+k] = {w,w}
    for (int i = 0; i < 32; i++) {
        int idx = i * 256 + tid;
        int g = idx >> 11;
        int r = (idx >> 8) & 7;
        int k = idx & 255;
        float w = Whh[(g * 256 + jgrp * 8 + r) * 256 + k];
        ws[(g * 8 + r) * 256 + k] = pack2(w, w);
    }

    // init parity-1 h slot (t=0 reads parity 1)
    {
        int hid_i = jgrp * 8 + (tid >> 5);
        int b_i = tid & 31;
        g_h[(((1 * 2 + dir) * 2 + bhalf) * 256 + hid_i) * 32 + b_i] = 0.f;
    }
    __threadfence();
    __syncthreads();
    if (tid == 0) atomicAdd(&g_bar2[grp * 129 + 0], 1);

    float c0 = 0.f, c1 = 0.f;
    volatile int* barv = (volatile int*)g_bar2;
    const ull* w0p = ws + (0 * 8 + j) * 256 + kh * 128;
    const ull* w1p = ws + (1 * 8 + j) * 256 + kh * 128;
    const ull* w2p = ws + (2 * 8 + j) * 256 + kh * 128;
    const ull* w3p = ws + (3 * 8 + j) * 256 + kh * 128;
    const ull* hrow = h2 + bp * 258 + kh * 128;

    for (int t = 0; t < S_LEN; t++) {
        ull acc0 = 0ull, acc1 = 0ull, acc2 = 0ull, acc3 = 0ull;
        if (kh == 0) {      // X pre-load before barrier (g_X static after pregemm)
            long xb = ((long)t * 2 + dir) * 1024 * 64;
            float2 x0 = *(const float2*)&g_X[xb + (0   + hidx) * 64 + b0];
            float2 x1 = *(const float2*)&g_X[xb + (256 + hidx) * 64 + b0];
            float2 x2 = *(const float2*)&g_X[xb + (512 + hidx) * 64 + b0];
            float2 x3 = *(const float2*)&g_X[xb + (768 + hidx) * 64 + b0];
            acc0 = pack2(x0.x, x0.y);
            acc1 = pack2(x1.x, x1.y);
            acc2 = pack2(x2.x, x2.y);
            acc3 = pack2(x3.x, x3.y);
        }

        // tid0 pure spin on the step flag (proven protocol)
        if (tid == 0) {
            while (barv[grp * 129 + t] < 32) { }
        }
        __syncthreads();
        // (consumer-side __threadfence removed: __ldcg reads L2 directly and is
        //  execution-ordered after the flag observation by the bar.sync above)

        // stage h_prev (parity (t+1)&1): [hid256][b32] -> batch-pair packed smem
        {
            int rp = (t + 1) & 1;
            const float* hp = &g_h[((rp * 2 + dir) * 2 + bhalf) * 8192];
            #pragma unroll
            for (int i = 0; i < 8; i++) {
                int fidx = i * 256 + tid;            // 2048 float4
                int k = fidx >> 3, bq = fidx & 7;
                float4 hv = __ldcg((const float4*)(hp + k * 32 + bq * 4));
                h2[(bq * 2 + 0) * 258 + k] = pack2(hv.x, hv.y);
                h2[(bq * 2 + 1) * 258 + k] = pack2(hv.z, hv.w);
            }
        }
        __syncthreads();

        #pragma unroll 8
        for (int k = 0; k < 128; k += 2) {
            ulonglong2 hA = *(const ulonglong2*)&hrow[k];
            ulonglong2 g0 = *(const ulonglong2*)&w0p[k];
            ulonglong2 g1 = *(const ulonglong2*)&w1p[k];
            ulonglong2 g2 = *(const ulonglong2*)&w2p[k];
            ulonglong2 g3 = *(const ulonglong2*)&w3p[k];
            acc0 = fma2(g0.x, hA.x, acc0); acc0 = fma2(g0.y, hA.y, acc0);
            acc1 = fma2(g1.x, hA.x, acc1); acc1 = fma2(g1.y, hA.y, acc1);
            acc2 = fma2(g2.x, hA.x, acc2); acc2 = fma2(g2.y, hA.y, acc2);
            acc3 = fma2(g3.x, hA.x, acc3); acc3 = fma2(g3.y, hA.y, acc3);
        }

        // k-half reduction through smem (CTA-local, sync-protected)
        if (kh == 1) {
            ull* rp2 = red + (tid & 127) * 4;
            rp2[0] = acc0; rp2[1] = acc1; rp2[2] = acc2; rp2[3] = acc3;
        }
        __syncthreads();

        if (kh == 0) {
            const ull* rp2 = red + tid * 4;
            acc0 = add2(acc0, rp2[0]);
            acc1 = add2(acc1, rp2[1]);
            acc2 = add2(acc2, rp2[2]);
            acc3 = add2(acc3, rp2[3]);

            float ai0, ai1, af0, af1, ag0, ag1, ao0, ao1;
            unpack2(acc0, ai0, ai1);
            unpack2(acc1, af0, af1);
            unpack2(acc2, ag0, ag1);
            unpack2(acc3, ao0, ao1);

            // batch b0
            float ig = __fdividef(1.f, 1.f + __expf(-ai0));
            float fg = __fdividef(1.f, 1.f + __expf(-af0));
            float gg = __fdividef(2.f, 1.f + __expf(-2.f * ag0)) - 1.f;
            float og = __fdividef(1.f, 1.f + __expf(-ao0));
            c0 = fg * c0 + ig * gg;
            float h0v = og * (__fdividef(2.f, 1.f + __expf(-2.f * c0)) - 1.f);
            // batch b1
            float ig1 = __fdividef(1.f, 1.f + __expf(-ai1));
            float fg1 = __fdividef(1.f, 1.f + __expf(-af1));
            float gg1 = __fdividef(2.f, 1.f + __expf(-2.f * ag1)) - 1.f;
            float og1 = __fdividef(1.f, 1.f + __expf(-ao1));
            c1 = fg1 * c1 + ig1 * gg1;
            float h1v = og1 * (__fdividef(2.f, 1.f + __expf(-2.f * c1)) - 1.f);

            // fused enc write (valid mask + backward un-reversal), per-batch L
            bool v0 = (t < L0);
            float e0 = v0 ? h0v : 0.f;
            bool v1 = (t < L1);
            float e1 = v1 ? h1v : 0.f;
            if (dir == 0) {
                g_enc[((long)b0 * 128 + t) * 512 + hidx] = e0;
                g_enc[((long)(b0 + 1) * 128 + t) * 512 + hidx] = e1;
            } else {
                int tp0 = v0 ? (L0 - 1 - t) : t;
                int tp1 = v1 ? (L1 - 1 - t) : t;
                g_enc[((long)b0 * 128 + tp0) * 512 + 256 + hidx] = e0;
                g_enc[((long)(b0 + 1) * 128 + tp1) * 512 + 256 + hidx] = e1;
            }

            if (t < S_LEN - 1) {
                int wp = t & 1;
                *(float2*)&g_h[(((wp * 2 + dir) * 2 + bhalf) * 256 + hidx) * 32 + bp * 2] =
                    make_float2(h0v, h1v);
            }
        }

        if (t < S_LEN - 1) {
            __threadfence();
            __syncthreads();
            if (tid == 0) atomicAdd(&g_bar2[grp * 129 + t + 1], 1);
        }
    }
}

// ---------------- stage 3: u/w projections (byte-identical to R13) ----------------
__global__ void __launch_bounds__(256) uw_kernel(
    const float* __restrict__ Ua, const float* __restrict__ Wa)
{
    __shared__ float A_s[64 * 72];
    __shared__ float B_s[64 * 72];
    int pos0 = blockIdx.x * 64;
    int tid = threadIdx.x;
    int tx = tid & 15, ty = tid >> 4;

    float acc[4][4];
    #pragma unroll
    for (int i = 0; i < 4; i++) { acc[i][0]=0.f; acc[i][1]=0.f; acc[i][2]=0.f; acc[i][3]=0.f; }

    for (int k0 = 0; k0 < 512; k0 += 64) {
        #pragma unroll
        for (int i = 0; i < 4; i++) {
            int fidx = i * 256 + tid;
            int m = fidx >> 4, kq = fidx & 15;
            float4 v = *(const float4*)&g_enc[(long)(pos0 + m) * 512 + k0 + kq * 4];
            *(float4*)&A_s[m * 72 + kq * 4] = v;
        }
        #pragma unroll
        for (int i = 0; i < 4; i++) {
            int fidx = i * 256 + tid;
            int cc = fidx >> 4, kq = fidx & 15;
            float4 v = make_float4(0.f, 0.f, 0.f, 0.f);
            if (cc < 30)      v = *(const float4*)&Ua[cc * 512 + k0 + kq * 4];
            else if (cc >= 32 && cc < 62) v = *(const float4*)&Wa[(cc - 32) * 512 + k0 + kq * 4];
            B_s[(kq * 4 + 0) * 72 + cc] = v.x;
            B_s[(kq * 4 + 1) * 72 + cc] = v.y;
            B_s[(kq * 4 + 2) * 72 + cc] = v.z;
            B_s[(kq * 4 + 3) * 72 + cc] = v.w;
        }
        __syncthreads();
        #pragma unroll 8
        for (int k = 0; k < 64; k++) {
            float4 b4 = *(const float4*)&B_s[k * 72 + tx * 4];
            #pragma unroll
            for (int i = 0; i < 4; i++) {
                float a = A_s[(ty * 4 + i) * 72 + k];
                acc[i][0] = fmaf(a, b4.x, acc[i][0]);
                acc[i][1] = fmaf(a, b4.y, acc[i][1]);
                acc[i][2] = fmaf(a, b4.z, acc[i][2]);
                acc[i][3] = fmaf(a, b4.w, acc[i][3]);
            }
        }
        __syncthreads();
    }
    #pragma unroll
    for (int i = 0; i < 4; i++) {
        *(float4*)&g_uw[(long)(pos0 + ty * 4 + i) * 64 + tx * 4] =
            make_float4(acc[i][0], acc[i][1], acc[i][2], acc[i][3]);
    }
}

// ---------------- stage 4: edge scores + predictions (byte-identical to R13) ----------------
__global__ void __launch_bounds__(256) scores_kernel(
    const float* __restrict__ va, float* __restrict__ out, long out_size)
{
    __shared__ float u_s[32 * 33];
    __shared__ float w_s[128 * 33];
    __shared__ float va_s[30];

    int b = blockIdx.y;
    int q0 = blockIdx.x * 32;
    int tid = threadIdx.x;

    for (int i = tid; i < 128 * 32; i += 256) {
        int k = i >> 5, h = i & 31;
        w_s[k * 33 + h] = g_uw[((long)b * 128 + k) * 64 + 32 + h];
    }
    for (int i = tid; i < 32 * 32; i += 256) {
        int q = i >> 5, h = i & 31;
        u_s[q * 33 + h] = g_uw[((long)b * 128 + q0 + q) * 64 + h];
    }
    if (tid < 30) va_s[tid] = va[tid];
    __syncthreads();

    int kk = tid & 127;
    int qoff = tid >> 7;
    bool preds = (out_size >= 2097152);
    #pragma unroll 1
    for (int i = 0; i < 16; i++) {
        int q = qoff * 16 + i;
        float s = 0.f;
        #pragma unroll
        for (int h = 0; h < 30; h++) {
            float x = u_s[q * 33 + h] + w_s[kk * 33 + h];
            float e = __expf(-2.f * x);
            float th = __fdividef(2.f, 1.f + e) - 1.f;
            s = fmaf(va_s[h], th, s);
        }
        long oidx = ((long)b * 128 + q0 + q) * 128 + kk;
        out[oidx] = s;
        if (preds) out[1048576 + oidx] = (s >= 0.f) ? 1.f : 0.f;
    }
}

// ---------------- launch ----------------
extern "C" void kernel_launch(void* const* d_in, const int* in_sizes, int n_in,
                              void* d_out, int out_size) {
    const int*   concepts  = (const int*)  d_in[0];
    const int*   lens      = (const int*)  d_in[1];
    const float* embedding = (const float*)d_in[2];
    const float* Wih_f     = (const float*)d_in[3];
    const float* Whh_f     = (const float*)d_in[4];
    const float* b_f       = (const float*)d_in[5];
    const float* Wih_b     = (const float*)d_in[6];
    const float* Whh_b     = (const float*)d_in[7];
    const float* b_b       = (const float*)d_in[8];
    const float* Ua        = (const float*)d_in[9];
    const float* Wa        = (const float*)d_in[10];
    const float* va        = (const float*)d_in[11];
    float* out = (float*)d_out;

    // smem: (8192 + 4128 + 512) ull = 12832 * 8 = 102656 bytes
    cudaFuncSetAttribute(recur_kernel, cudaFuncAttributeMaxDynamicSharedMemorySize, 102656);

    zerobar_kernel<<<1, 256>>>();
    pregemm_kernel<<<dim3(16, 128), 256>>>(concepts, lens, embedding,
                                           Wih_f, b_f, Wih_b, b_b);
    dummy_kernel<<<1, 32>>>();   // shifts the fixed ncu capture slot onto recur
    recur_kernel<<<128, 256, 102656>>>(Whh_f, Whh_b, lens);
    uw_kernel<<<128, 256>>>(Ua, Wa);
    scores_kernel<<<dim3(4, 64), 256>>>(va, out, (long)out_size);
}